// round 14
// baseline (speedup 1.0000x reference)
#include <cuda_runtime.h>
#include <cstdint>

// Inv1x1MM_SVD, C=16, 65536 positions.
// 2-lane row-slab layout (R10) with the U and V QRs FUSED step-by-step in one
// warp: two independent dependency chains per step (dot->shfl->rcp->update)
// overlap, doubling per-warp ILP in the latency-bound regime. Both QRs write
// 1/||b_k|| to shared memory; w is built entirely in the epilogue.

constexpr int NPOS = 8 * 8192;

#define FMA2(d, a, b, c) asm("fma.rn.f32x2 %0, %1, %2, %3;" : "=l"(d) : "l"(a), "l"(b), "l"(c))
#define MUL2(d, a, b)    asm("mul.rn.f32x2 %0, %1, %2;"     : "=l"(d) : "l"(a), "l"(b))
#define ADD2(d, a, b)    asm("add.rn.f32x2 %0, %1, %2;"     : "=l"(d) : "l"(a), "l"(b))
#define PACK2(d, lo, hi) asm("mov.b64 %0, {%1, %2};"        : "=l"(d) : "f"(lo), "f"(hi))
#define UNPACK2(lo, hi, d) asm("mov.b64 {%0, %1}, %2;" : "=f"(lo), "=f"(hi) : "l"(d))

__device__ __forceinline__ uint64_t shx1(uint64_t v) {
    uint32_t lo, hi;
    asm("mov.b64 {%0, %1}, %2;" : "=r"(lo), "=r"(hi) : "l"(v));
    lo = __shfl_xor_sync(0xffffffffu, lo, 1);
    hi = __shfl_xor_sync(0xffffffffu, hi, 1);
    uint64_t r;
    asm("mov.b64 %0, {%1, %2};" : "=l"(r) : "r"(lo), "r"(hi));
    return r;
}
__device__ __forceinline__ float frcp(float x) {
    float r;
    asm("rcp.approx.f32 %0, %1;" : "=f"(r) : "f"(x));
    return r;
}

__device__ __forceinline__ void load_mat(uint64_t (&A)[8][8], const float4* f4, int rbase) {
    #pragma unroll
    for (int i = 0; i < 8; i++) {
        const float4 q0 = __ldg(&f4[rbase + 4 * i + 0]);
        const float4 q1 = __ldg(&f4[rbase + 4 * i + 1]);
        const float4 q2 = __ldg(&f4[rbase + 4 * i + 2]);
        const float4 q3 = __ldg(&f4[rbase + 4 * i + 3]);
        PACK2(A[i][0], q0.x, q0.y); PACK2(A[i][1], q0.z, q0.w);
        PACK2(A[i][2], q1.x, q1.y); PACK2(A[i][3], q1.z, q1.w);
        PACK2(A[i][4], q2.x, q2.y); PACK2(A[i][5], q2.z, q2.w);
        PACK2(A[i][6], q3.x, q3.y); PACK2(A[i][7], q3.z, q3.w);
    }
}

__global__ void __launch_bounds__(64, 5)
inv1x1mm_svd_kernel(const float* __restrict__ data,
                    const float* __restrict__ paras,
                    float* __restrict__ out) {
    __shared__ float rsU[32][17];   // 1/||b0_k||, stride-17 conflict-free
    __shared__ float rsV[32][17];   // 1/||b1_k||

    const int tid  = threadIdx.x;
    const int half = tid & 1;
    const int p    = tid >> 1;
    const int pos  = blockIdx.x * 32 + p;

    const float4* f4 = (const float4*)(paras + (size_t)pos * 528);
    const bool writer = (half == 0);

    uint64_t AU[8][8], AV[8][8];
    load_mat(AU, f4, 4 + half * 32);
    load_mat(AV, f4, 68 + half * 32);

    // ===== fused MGS over U and V: two independent chains per step =====
    #pragma unroll
    for (int k = 0; k < 15; k++) {
        const int c0 = k >> 1;
        const int cu = (k + 1) >> 1;

        uint64_t akU[8], akV[8];
        #pragma unroll
        for (int i = 0; i < 8; i++) {
            float lo, hi, x;
            UNPACK2(lo, hi, AU[i][c0]);
            x = (k & 1) ? hi : lo;
            PACK2(akU[i], x, x);
            UNPACK2(lo, hi, AV[i][c0]);
            x = (k & 1) ? hi : lo;
            PACK2(akV[i], x, x);
        }

        uint64_t ppU[8], ppV[8];
        #pragma unroll
        for (int c = c0; c < 8; c++) {
            uint64_t s0, s1, t0, t1;
            MUL2(s0, akU[0], AU[0][c]);
            MUL2(t0, akV[0], AV[0][c]);
            MUL2(s1, akU[4], AU[4][c]);
            MUL2(t1, akV[4], AV[4][c]);
            FMA2(s0, akU[1], AU[1][c], s0);
            FMA2(t0, akV[1], AV[1][c], t0);
            FMA2(s1, akU[5], AU[5][c], s1);
            FMA2(t1, akV[5], AV[5][c], t1);
            FMA2(s0, akU[2], AU[2][c], s0);
            FMA2(t0, akV[2], AV[2][c], t0);
            FMA2(s1, akU[6], AU[6][c], s1);
            FMA2(t1, akV[6], AV[6][c], t1);
            FMA2(s0, akU[3], AU[3][c], s0);
            FMA2(t0, akV[3], AV[3][c], t0);
            FMA2(s1, akU[7], AU[7][c], s1);
            FMA2(t1, akV[7], AV[7][c], t1);
            ADD2(s0, s0, s1);
            ADD2(t0, t0, t1);
            const uint64_t so = shx1(s0);
            const uint64_t to = shx1(t0);
            ADD2(ppU[c], s0, so);
            ADD2(ppV[c], t0, to);
        }

        // fresh norms, parallel MUFU paths for the two matrices
        float lo, hi;
        UNPACK2(lo, hi, ppU[c0]);
        const float pkU = fmaxf((k & 1) ? hi : lo, 1e-30f);
        UNPACK2(lo, hi, ppV[c0]);
        const float pkV = fmaxf((k & 1) ? hi : lo, 1e-30f);
        const float niU = -frcp(pkU);
        const float niV = -frcp(pkV);
        if (writer) {
            rsU[p][k] = rsqrtf(pkU);
            rsV[p][k] = rsqrtf(pkV);
        }
        uint64_t nU, nV;
        PACK2(nU, niU, niU);
        PACK2(nV, niV, niV);

        #pragma unroll
        for (int c = cu; c < 8; c++) {
            uint64_t sU, sV;
            MUL2(sU, ppU[c], nU);
            MUL2(sV, ppV[c], nV);
            if (!(k & 1) && c == cu) {        // pair contains j == k: mask lo half
                float sl, sh;
                UNPACK2(sl, sh, sU);
                PACK2(sU, 0.0f, sh);
                UNPACK2(sl, sh, sV);
                PACK2(sV, 0.0f, sh);
            }
            #pragma unroll
            for (int i = 0; i < 8; i++) {
                FMA2(AU[i][c], sU, akU[i], AU[i][c]);
                FMA2(AV[i][c], sV, akV[i], AV[i][c]);
            }
        }
    }
    // column 15 norms
    {
        float nU15 = 0.0f, nV15 = 0.0f;
        #pragma unroll
        for (int i = 0; i < 8; i++) {
            float lo, hi;
            UNPACK2(lo, hi, AU[i][7]);
            nU15 = fmaf(hi, hi, nU15);
            UNPACK2(lo, hi, AV[i][7]);
            nV15 = fmaf(hi, hi, nV15);
        }
        nU15 += __shfl_xor_sync(0xffffffffu, nU15, 1);
        nV15 += __shfl_xor_sync(0xffffffffu, nV15, 1);
        if (writer) {
            rsU[p][15] = rsqrtf(fmaxf(nU15, 1e-30f));
            rsV[p][15] = rsqrtf(fmaxf(nV15, 1e-30f));
        }
    }

    // ===== epilogue =====
    const float4 d0 = __ldg((const float4*)(data + pos * 16 + half * 8));
    const float4 d1 = __ldg((const float4*)(data + pos * 16 + half * 8 + 4));
    uint64_t dd[8];
    PACK2(dd[0], d0.x, d0.x); PACK2(dd[1], d0.y, d0.y);
    PACK2(dd[2], d0.z, d0.z); PACK2(dd[3], d0.w, d0.w);
    PACK2(dd[4], d1.x, d1.x); PACK2(dd[5], d1.y, d1.y);
    PACK2(dd[6], d1.z, d1.z); PACK2(dd[7], d1.w, d1.w);

    __syncwarp();   // partner's rsU/rsV stores -> my reads
    uint64_t w[8];
    #pragma unroll
    for (int c = 0; c < 8; c++) {
        uint64_t s0, s1;
        MUL2(s0, dd[0], AU[0][c]);
        MUL2(s1, dd[4], AU[4][c]);
        FMA2(s0, dd[1], AU[1][c], s0);
        FMA2(s1, dd[5], AU[5][c], s1);
        FMA2(s0, dd[2], AU[2][c], s0);
        FMA2(s1, dd[6], AU[6][c], s1);
        FMA2(s0, dd[3], AU[3][c], s0);
        FMA2(s1, dd[7], AU[7][c], s1);
        ADD2(s0, s0, s1);
        const uint64_t o = shx1(s0);
        ADD2(s0, s0, o);   // full v pair
        const float2 lsp = __ldg((const float2*)(paras + (size_t)pos * 528 + 2 * c));
        uint64_t m;
        PACK2(m, __expf(lsp.x) * rsU[p][2 * c] * rsV[p][2 * c],
                 __expf(lsp.y) * rsU[p][2 * c + 1] * rsV[p][2 * c + 1]);
        MUL2(w[c], s0, m);
    }

    // res_d = sum_j w_j * b1[d][j]  (d = my 8 local rows)
    float o[8];
    #pragma unroll
    for (int i = 0; i < 8; i++) {
        uint64_t s0, s1;
        MUL2(s0, w[0], AV[i][0]);
        MUL2(s1, w[4], AV[i][4]);
        FMA2(s0, w[1], AV[i][1], s0);
        FMA2(s1, w[5], AV[i][5], s1);
        FMA2(s0, w[2], AV[i][2], s0);
        FMA2(s1, w[6], AV[i][6], s1);
        FMA2(s0, w[3], AV[i][3], s0);
        FMA2(s1, w[7], AV[i][7], s1);
        ADD2(s0, s0, s1);
        float lo, hi;
        UNPACK2(lo, hi, s0);
        o[i] = lo + hi;
    }

    float4* o4 = (float4*)(out + pos * 16 + half * 8);
    o4[0] = make_float4(o[0], o[1], o[2], o[3]);
    o4[1] = make_float4(o[4], o[5], o[6], o[7]);
}

extern "C" void kernel_launch(void* const* d_in, const int* in_sizes, int n_in,
                              void* d_out, int out_size) {
    const float* data  = (const float*)d_in[0];
    const float* paras = (const float*)d_in[1];
    if (n_in >= 2 && in_sizes[0] > in_sizes[1]) {  // defensive ordering by size
        data  = (const float*)d_in[1];
        paras = (const float*)d_in[0];
    }
    inv1x1mm_svd_kernel<<<NPOS / 32, 64>>>(data, paras, (float*)d_out);
}

// round 15
// speedup vs baseline: 1.9193x; 1.9193x over previous
#include <cuda_runtime.h>
#include <cstdint>

// Inv1x1MM_SVD, C=16, 65536 positions.
// R10 base (2-lane row-slab MGS, fresh norms, rs0->smem, rs1 folded into w)
// + cp.async staging of the V matrices: each warp prefetches its 16 positions'
// V tiles into smem with coalesced 16B async copies (no registers, L1-bypass)
// at kernel entry; the copy completes under the U QR. This removes ~1000
// scattered-LDG L1 wavefronts per warp - the dominant cost in R10's profile.

constexpr int NPOS = 8 * 8192;

#define FMA2(d, a, b, c) asm("fma.rn.f32x2 %0, %1, %2, %3;" : "=l"(d) : "l"(a), "l"(b), "l"(c))
#define MUL2(d, a, b)    asm("mul.rn.f32x2 %0, %1, %2;"     : "=l"(d) : "l"(a), "l"(b))
#define ADD2(d, a, b)    asm("add.rn.f32x2 %0, %1, %2;"     : "=l"(d) : "l"(a), "l"(b))
#define PACK2(d, lo, hi) asm("mov.b64 %0, {%1, %2};"        : "=l"(d) : "f"(lo), "f"(hi))
#define UNPACK2(lo, hi, d) asm("mov.b64 {%0, %1}, %2;" : "=f"(lo), "=f"(hi) : "l"(d))

__device__ __forceinline__ uint32_t smem_u32(const void* p) {
    uint32_t a;
    asm("{ .reg .u64 t; cvta.to.shared.u64 t, %1; cvt.u32.u64 %0, t; }" : "=r"(a) : "l"(p));
    return a;
}
__device__ __forceinline__ uint64_t shx1(uint64_t v) {
    uint32_t lo, hi;
    asm("mov.b64 {%0, %1}, %2;" : "=r"(lo), "=r"(hi) : "l"(v));
    lo = __shfl_xor_sync(0xffffffffu, lo, 1);
    hi = __shfl_xor_sync(0xffffffffu, hi, 1);
    uint64_t r;
    asm("mov.b64 %0, {%1, %2};" : "=l"(r) : "r"(lo), "r"(hi));
    return r;
}
__device__ __forceinline__ float frcp(float x) {
    float r;
    asm("rcp.approx.f32 %0, %1;" : "=f"(r) : "f"(x));
    return r;
}

// MGS, rows split across a lane pair.
// SCALEW=false: writer lane stores 1/||b_k|| to rs_sm[k].
// SCALEW=true : fold 1/||b_k|| into w element k as columns finish.
template <bool SCALEW>
__device__ __forceinline__ void mgs2(uint64_t (&A)[8][8], uint64_t* w,
                                     float* rs_sm, bool writer) {
    #pragma unroll
    for (int k = 0; k < 15; k++) {
        const int c0 = k >> 1;
        const int cu = (k + 1) >> 1;

        uint64_t ak[8];
        #pragma unroll
        for (int i = 0; i < 8; i++) {
            float lo, hi;
            UNPACK2(lo, hi, A[i][c0]);
            const float x = (k & 1) ? hi : lo;
            PACK2(ak[i], x, x);
        }

        uint64_t pp[8];
        #pragma unroll
        for (int c = c0; c < 8; c++) {
            uint64_t s0, s1;
            MUL2(s0, ak[0], A[0][c]);
            MUL2(s1, ak[4], A[4][c]);
            FMA2(s0, ak[1], A[1][c], s0);
            FMA2(s1, ak[5], A[5][c], s1);
            FMA2(s0, ak[2], A[2][c], s0);
            FMA2(s1, ak[6], A[6][c], s1);
            FMA2(s0, ak[3], A[3][c], s0);
            FMA2(s1, ak[7], A[7][c], s1);
            ADD2(s0, s0, s1);
            const uint64_t o = shx1(s0);
            ADD2(pp[c], s0, o);
        }

        float plo, phi;
        UNPACK2(plo, phi, pp[c0]);
        const float pk = fmaxf((k & 1) ? phi : plo, 1e-30f);
        const float ninv = -frcp(pk);        // projection path (MUFU.RCP)
        const float r = rsqrtf(pk);          // normalization path (parallel)
        if (SCALEW) {
            float wl, wh;
            UNPACK2(wl, wh, w[c0]);
            if (k & 1) wh *= r; else wl *= r;
            PACK2(w[c0], wl, wh);
        } else if (writer) {
            rs_sm[k] = r;
        }
        uint64_t n2;
        PACK2(n2, ninv, ninv);

        #pragma unroll
        for (int c = cu; c < 8; c++) {
            uint64_t s;
            MUL2(s, pp[c], n2);
            if (!(k & 1) && c == cu) {       // pair contains j == k: mask lo half
                float sl, sh;
                UNPACK2(sl, sh, s);
                PACK2(s, 0.0f, sh);
            }
            #pragma unroll
            for (int i = 0; i < 8; i++) FMA2(A[i][c], s, ak[i], A[i][c]);
        }
    }
    float n15 = 0.0f;
    #pragma unroll
    for (int i = 0; i < 8; i++) {
        float lo, hi;
        UNPACK2(lo, hi, A[i][7]);
        n15 = fmaf(hi, hi, n15);
    }
    n15 += __shfl_xor_sync(0xffffffffu, n15, 1);
    const float r = rsqrtf(fmaxf(n15, 1e-30f));
    if (SCALEW) {
        float wl, wh;
        UNPACK2(wl, wh, w[7]);
        wh *= r;
        PACK2(w[7], wl, wh);
    } else if (writer) {
        rs_sm[15] = r;
    }
}

__device__ __forceinline__ void load_mat(uint64_t (&A)[8][8], const float4* f4, int rbase) {
    #pragma unroll
    for (int i = 0; i < 8; i++) {
        const float4 q0 = __ldg(&f4[rbase + 4 * i + 0]);
        const float4 q1 = __ldg(&f4[rbase + 4 * i + 1]);
        const float4 q2 = __ldg(&f4[rbase + 4 * i + 2]);
        const float4 q3 = __ldg(&f4[rbase + 4 * i + 3]);
        PACK2(A[i][0], q0.x, q0.y); PACK2(A[i][1], q0.z, q0.w);
        PACK2(A[i][2], q1.x, q1.y); PACK2(A[i][3], q1.z, q1.w);
        PACK2(A[i][4], q2.x, q2.y); PACK2(A[i][5], q2.z, q2.w);
        PACK2(A[i][6], q3.x, q3.y); PACK2(A[i][7], q3.z, q3.w);
    }
}

// read my 8-row slab from the staged smem V buffer (32 consecutive float4)
__device__ __forceinline__ void load_mat_sm(uint64_t (&A)[8][8], const float4* slab) {
    #pragma unroll
    for (int i = 0; i < 8; i++) {
        const float4 q0 = slab[4 * i + 0];
        const float4 q1 = slab[4 * i + 1];
        const float4 q2 = slab[4 * i + 2];
        const float4 q3 = slab[4 * i + 3];
        PACK2(A[i][0], q0.x, q0.y); PACK2(A[i][1], q0.z, q0.w);
        PACK2(A[i][2], q1.x, q1.y); PACK2(A[i][3], q1.z, q1.w);
        PACK2(A[i][4], q2.x, q2.y); PACK2(A[i][5], q2.z, q2.w);
        PACK2(A[i][6], q3.x, q3.y); PACK2(A[i][7], q3.z, q3.w);
    }
}

__global__ void __launch_bounds__(64, 6)
inv1x1mm_svd_kernel(const float* __restrict__ data,
                    const float* __restrict__ paras,
                    float* __restrict__ out) {
    // V staging: per position 67 float4 (2 slabs of 32 at offsets 0 and 33,
    // stride 67 => 268 words, 12 mod 32 -> 2-way LDS conflicts max).
    __shared__ __align__(16) float4 vbuf[32 * 67];
    __shared__ float rs_sm[32][17];          // U inverse norms, stride-17

    const int tid    = threadIdx.x;
    const int lane   = tid & 31;
    const int warpid = tid >> 5;
    const int half   = tid & 1;
    const int p      = tid >> 1;
    const int pos    = blockIdx.x * 32 + p;

    const float4* f4 = (const float4*)paras + (size_t)pos * 132;

    // ---- stage V tiles for this warp's 16 positions via cp.async.cg ----
    // iter m covers position (warpbase+m): two 512B halves, consecutive lanes
    // -> consecutive 16B chunks (4 lines per instruction, L2-direct fill).
    {
        const size_t pw = (size_t)(blockIdx.x * 32 + warpid * 16);
        const char* src = (const char*)((const float4*)paras + pw * 132 + 68 + lane);
        uint32_t dst = smem_u32(&vbuf[warpid * 16 * 67 + lane]);
        #pragma unroll 4
        for (int m = 0; m < 16; m++) {
            asm volatile("cp.async.cg.shared.global [%0], [%1], 16;"
                         :: "r"(dst), "l"(src) : "memory");
            asm volatile("cp.async.cg.shared.global [%0], [%1], 16;"
                         :: "r"(dst + 528u), "l"(src + 512) : "memory");
            src += 2112;       // next position (132 float4)
            dst += 1072u;      // next position (67 float4)
        }
        asm volatile("cp.async.commit_group;" ::: "memory");
    }

    uint64_t A[8][8];

    // ===== QR of U =====  (direct LDG; rs0 -> rs_sm)
    load_mat(A, f4, 4 + half * 32);
    mgs2<false>(A, nullptr, rs_sm[p], half == 0);

    // local partial dots v_j against U's Q
    const float4 d0 = __ldg((const float4*)(data + pos * 16 + half * 8));
    const float4 d1 = __ldg((const float4*)(data + pos * 16 + half * 8 + 4));
    uint64_t dd[8];
    PACK2(dd[0], d0.x, d0.x); PACK2(dd[1], d0.y, d0.y);
    PACK2(dd[2], d0.z, d0.z); PACK2(dd[3], d0.w, d0.w);
    PACK2(dd[4], d1.x, d1.x); PACK2(dd[5], d1.y, d1.y);
    PACK2(dd[6], d1.z, d1.z); PACK2(dd[7], d1.w, d1.w);

    uint64_t w[8];
    #pragma unroll
    for (int c = 0; c < 8; c++) {
        uint64_t s0, s1;
        MUL2(s0, dd[0], A[0][c]);
        MUL2(s1, dd[4], A[4][c]);
        FMA2(s0, dd[1], A[1][c], s0);
        FMA2(s1, dd[5], A[5][c], s1);
        FMA2(s0, dd[2], A[2][c], s0);
        FMA2(s1, dd[6], A[6][c], s1);
        FMA2(s0, dd[3], A[3][c], s0);
        FMA2(s1, dd[7], A[7][c], s1);
        ADD2(w[c], s0, s1);
    }

    __syncwarp();   // partner's rs_sm writes -> my reads
    #pragma unroll
    for (int c = 0; c < 8; c++) {
        const uint64_t o = shx1(w[c]);
        ADD2(w[c], w[c], o);
        const float2 lsp = __ldg((const float2*)f4 + c);   // ls pair {2c, 2c+1}
        uint64_t m;
        PACK2(m, __expf(lsp.x) * rs_sm[p][2 * c],
                 __expf(lsp.y) * rs_sm[p][2 * c + 1]);
        MUL2(w[c], w[c], m);
    }

    // ===== QR of V =====  (staged tile; folds 1/||b1_j|| into w)
    asm volatile("cp.async.wait_group 0;" ::: "memory");
    __syncwarp();   // all lanes' async copies visible warp-wide
    load_mat_sm(A, &vbuf[p * 67 + 33 * half]);
    mgs2<true>(A, w, nullptr, false);

    // res_d = sum_j w_j * b1[d][j]  (d = my 8 local rows)
    float o[8];
    #pragma unroll
    for (int i = 0; i < 8; i++) {
        uint64_t s0, s1;
        MUL2(s0, w[0], A[i][0]);
        MUL2(s1, w[4], A[i][4]);
        FMA2(s0, w[1], A[i][1], s0);
        FMA2(s1, w[5], A[i][5], s1);
        FMA2(s0, w[2], A[i][2], s0);
        FMA2(s1, w[6], A[i][6], s1);
        FMA2(s0, w[3], A[i][3], s0);
        FMA2(s1, w[7], A[i][7], s1);
        ADD2(s0, s0, s1);
        float lo, hi;
        UNPACK2(lo, hi, s0);
        o[i] = lo + hi;
    }

    float4* o4 = (float4*)(out + pos * 16 + half * 8);
    o4[0] = make_float4(o[0], o[1], o[2], o[3]);
    o4[1] = make_float4(o[4], o[5], o[6], o[7]);
}

extern "C" void kernel_launch(void* const* d_in, const int* in_sizes, int n_in,
                              void* d_out, int out_size) {
    const float* data  = (const float*)d_in[0];
    const float* paras = (const float*)d_in[1];
    if (n_in >= 2 && in_sizes[0] > in_sizes[1]) {  // defensive ordering by size
        data  = (const float*)d_in[1];
        paras = (const float*)d_in[0];
    }
    inv1x1mm_svd_kernel<<<NPOS / 32, 64>>>(data, paras, (float*)d_out);
}

// round 16
// speedup vs baseline: 2.6159x; 1.3630x over previous
#include <cuda_runtime.h>
#include <cstdint>

// Inv1x1MM_SVD, C=16, 65536 positions.
// R10 skeleton (2-lane row-slab, rs0->smem, rs1 folded into w) with BLOCK-2
// MGS: columns processed in pairs {2t,2t+1}. The duplicated (x,x)/(y,y)
// registers serve as both dot operands and update directions, halving the
// extraction overhead; later pairs get one combined rank-2 update. Norms are
// fresh (n00 from the live dot; n11' recomputed after the in-pair step).

constexpr int NPOS = 8 * 8192;

#define FMA2(d, a, b, c) asm("fma.rn.f32x2 %0, %1, %2, %3;" : "=l"(d) : "l"(a), "l"(b), "l"(c))
#define MUL2(d, a, b)    asm("mul.rn.f32x2 %0, %1, %2;"     : "=l"(d) : "l"(a), "l"(b))
#define ADD2(d, a, b)    asm("add.rn.f32x2 %0, %1, %2;"     : "=l"(d) : "l"(a), "l"(b))
#define PACK2(d, lo, hi) asm("mov.b64 %0, {%1, %2};"        : "=l"(d) : "f"(lo), "f"(hi))
#define UNPACK2(lo, hi, d) asm("mov.b64 {%0, %1}, %2;" : "=f"(lo), "=f"(hi) : "l"(d))

__device__ __forceinline__ uint64_t shx1(uint64_t v) {
    uint32_t lo, hi;
    asm("mov.b64 {%0, %1}, %2;" : "=r"(lo), "=r"(hi) : "l"(v));
    lo = __shfl_xor_sync(0xffffffffu, lo, 1);
    hi = __shfl_xor_sync(0xffffffffu, hi, 1);
    uint64_t r;
    asm("mov.b64 %0, {%1, %2};" : "=l"(r) : "r"(lo), "r"(hi));
    return r;
}
__device__ __forceinline__ float frcp(float x) {
    float r;
    asm("rcp.approx.f32 %0, %1;" : "=f"(r) : "f"(x));
    return r;
}

// Block-2 MGS, rows split across a lane pair.
// SCALEW=false: writer lane stores 1/||b|| pair to rs_sm[2t], rs_sm[2t+1].
// SCALEW=true : fold the 1/||b|| pair into w[t] as the pair finishes.
template <bool SCALEW>
__device__ __forceinline__ void mgs2b(uint64_t (&A)[8][8], uint64_t* w,
                                      float* rs_sm, bool writer) {
    #pragma unroll
    for (int t = 0; t < 8; t++) {
        // duplicate pair t's columns: ax = (x,x) (col 2t), ay = (y,y) (col 2t+1)
        uint64_t ax[8], ay[8];
        #pragma unroll
        for (int i = 0; i < 8; i++) {
            float lo, hi;
            UNPACK2(lo, hi, A[i][t]);
            PACK2(ax[i], lo, lo);
            PACK2(ay[i], hi, hi);
        }

        // pair-internal dots: (n00, d01) = sum_i ax_i * A[i][t]
        uint64_t s0, s1;
        MUL2(s0, ax[0], A[0][t]);
        MUL2(s1, ax[4], A[4][t]);
        FMA2(s0, ax[1], A[1][t], s0);
        FMA2(s1, ax[5], A[5][t], s1);
        FMA2(s0, ax[2], A[2][t], s0);
        FMA2(s1, ax[6], A[6][t], s1);
        FMA2(s0, ax[3], A[3][t], s0);
        FMA2(s1, ax[7], A[7][t], s1);
        ADD2(s0, s0, s1);
        const uint64_t o0 = shx1(s0);
        ADD2(s0, s0, o0);
        float n00, d01;
        UNPACK2(n00, d01, s0);
        n00 = fmaxf(n00, 1e-30f);
        const float i00 = frcp(n00);       // projection scale path
        const float r0  = rsqrtf(n00);     // normalization path (parallel MUFU)
        const float s01 = d01 * i00;

        // col 2t+1 -= s01 * col 2t  (masked in A); ay := ay' = y - s01*x
        uint64_t m01, ms;
        PACK2(m01, 0.0f, -s01);
        PACK2(ms, -s01, -s01);
        #pragma unroll
        for (int i = 0; i < 8; i++) {
            FMA2(A[i][t], m01, ax[i], A[i][t]);
            FMA2(ay[i], ms, ax[i], ay[i]);
        }

        // fresh n11' = ||c2t+1'||^2  (ay halves identical -> scalar reduce)
        float nb;
        {
            uint64_t b0, b1;
            MUL2(b0, ay[0], ay[0]);
            MUL2(b1, ay[4], ay[4]);
            FMA2(b0, ay[1], ay[1], b0);
            FMA2(b1, ay[5], ay[5], b1);
            FMA2(b0, ay[2], ay[2], b0);
            FMA2(b1, ay[6], ay[6], b1);
            FMA2(b0, ay[3], ay[3], b0);
            FMA2(b1, ay[7], ay[7], b1);
            ADD2(b0, b0, b1);
            float l, h;
            UNPACK2(l, h, b0);
            nb = l + __shfl_xor_sync(0xffffffffu, l, 1);
        }
        nb = fmaxf(nb, 1e-30f);
        const float i11 = frcp(nb);
        const float r1  = rsqrtf(nb);

        if (SCALEW) {
            float wl, wh;
            UNPACK2(wl, wh, w[t]);
            wl *= r0;
            wh *= r1;
            PACK2(w[t], wl, wh);
        } else if (writer) {
            rs_sm[2 * t]     = r0;
            rs_sm[2 * t + 1] = r1;
        }

        // combined rank-2 update of all later pairs:
        // c_j -= (<ax,c_j>/n00) ax + (<ay',c_j>/n11') ay'
        uint64_t ni0, ni1;
        PACK2(ni0, -i00, -i00);
        PACK2(ni1, -i11, -i11);
        #pragma unroll
        for (int c = t + 1; c < 8; c++) {
            uint64_t sA0, sA1, sB0, sB1;
            MUL2(sA0, ax[0], A[0][c]);
            MUL2(sB0, ay[0], A[0][c]);
            MUL2(sA1, ax[4], A[4][c]);
            MUL2(sB1, ay[4], A[4][c]);
            FMA2(sA0, ax[1], A[1][c], sA0);
            FMA2(sB0, ay[1], A[1][c], sB0);
            FMA2(sA1, ax[5], A[5][c], sA1);
            FMA2(sB1, ay[5], A[5][c], sB1);
            FMA2(sA0, ax[2], A[2][c], sA0);
            FMA2(sB0, ay[2], A[2][c], sB0);
            FMA2(sA1, ax[6], A[6][c], sA1);
            FMA2(sB1, ay[6], A[6][c], sB1);
            FMA2(sA0, ax[3], A[3][c], sA0);
            FMA2(sB0, ay[3], A[3][c], sB0);
            FMA2(sA1, ax[7], A[7][c], sA1);
            FMA2(sB1, ay[7], A[7][c], sB1);
            ADD2(sA0, sA0, sA1);
            ADD2(sB0, sB0, sB1);
            const uint64_t oA = shx1(sA0);
            const uint64_t oB = shx1(sB0);
            ADD2(sA0, sA0, oA);
            ADD2(sB0, sB0, oB);
            uint64_t al, be;
            MUL2(al, sA0, ni0);
            MUL2(be, sB0, ni1);
            #pragma unroll
            for (int i = 0; i < 8; i++) {
                FMA2(A[i][c], al, ax[i], A[i][c]);
                FMA2(A[i][c], be, ay[i], A[i][c]);
            }
        }
    }
}

__device__ __forceinline__ void load_mat(uint64_t (&A)[8][8], const float4* f4, int rbase) {
    #pragma unroll
    for (int i = 0; i < 8; i++) {
        const float4 q0 = __ldg(&f4[rbase + 4 * i + 0]);
        const float4 q1 = __ldg(&f4[rbase + 4 * i + 1]);
        const float4 q2 = __ldg(&f4[rbase + 4 * i + 2]);
        const float4 q3 = __ldg(&f4[rbase + 4 * i + 3]);
        PACK2(A[i][0], q0.x, q0.y); PACK2(A[i][1], q0.z, q0.w);
        PACK2(A[i][2], q1.x, q1.y); PACK2(A[i][3], q1.z, q1.w);
        PACK2(A[i][4], q2.x, q2.y); PACK2(A[i][5], q2.z, q2.w);
        PACK2(A[i][6], q3.x, q3.y); PACK2(A[i][7], q3.z, q3.w);
    }
}

__global__ void __launch_bounds__(64, 6)
inv1x1mm_svd_kernel(const float* __restrict__ data,
                    const float* __restrict__ paras,
                    float* __restrict__ out) {
    __shared__ float rs_sm[32][17];          // U inverse norms, stride-17

    const int tid  = threadIdx.x;
    const int half = tid & 1;
    const int p    = tid >> 1;
    const int pos  = blockIdx.x * 32 + p;

    const float4* f4 = (const float4*)paras + (size_t)pos * 132;

    uint64_t A[8][8];

    // ===== QR of U =====  (rs0 -> rs_sm)
    load_mat(A, f4, 4 + half * 32);
    mgs2b<false>(A, nullptr, rs_sm[p], half == 0);

    // local partial dots v_j against U's Q
    const float4 d0 = __ldg((const float4*)(data + pos * 16 + half * 8));
    const float4 d1 = __ldg((const float4*)(data + pos * 16 + half * 8 + 4));
    uint64_t dd[8];
    PACK2(dd[0], d0.x, d0.x); PACK2(dd[1], d0.y, d0.y);
    PACK2(dd[2], d0.z, d0.z); PACK2(dd[3], d0.w, d0.w);
    PACK2(dd[4], d1.x, d1.x); PACK2(dd[5], d1.y, d1.y);
    PACK2(dd[6], d1.z, d1.z); PACK2(dd[7], d1.w, d1.w);

    uint64_t w[8];
    #pragma unroll
    for (int c = 0; c < 8; c++) {
        uint64_t s0, s1;
        MUL2(s0, dd[0], A[0][c]);
        MUL2(s1, dd[4], A[4][c]);
        FMA2(s0, dd[1], A[1][c], s0);
        FMA2(s1, dd[5], A[5][c], s1);
        FMA2(s0, dd[2], A[2][c], s0);
        FMA2(s1, dd[6], A[6][c], s1);
        FMA2(s0, dd[3], A[3][c], s0);
        FMA2(s1, dd[7], A[7][c], s1);
        ADD2(w[c], s0, s1);
    }

    // reload A with V now; the reduce/exp below hides the LDG latency
    load_mat(A, f4, 68 + half * 32);

    __syncwarp();   // partner's rs_sm writes -> my reads
    #pragma unroll
    for (int c = 0; c < 8; c++) {
        const uint64_t o = shx1(w[c]);
        ADD2(w[c], w[c], o);
        const float2 lsp = __ldg((const float2*)f4 + c);   // ls pair {2c, 2c+1}
        uint64_t m;
        PACK2(m, __expf(lsp.x) * rs_sm[p][2 * c],
                 __expf(lsp.y) * rs_sm[p][2 * c + 1]);
        MUL2(w[c], w[c], m);
    }

    // ===== QR of V =====  (folds 1/||b1_j|| into w)
    mgs2b<true>(A, w, nullptr, false);

    // res_d = sum_j w_j * b1[d][j]  (d = my 8 local rows)
    float o[8];
    #pragma unroll
    for (int i = 0; i < 8; i++) {
        uint64_t s0, s1;
        MUL2(s0, w[0], A[i][0]);
        MUL2(s1, w[4], A[i][4]);
        FMA2(s0, w[1], A[i][1], s0);
        FMA2(s1, w[5], A[i][5], s1);
        FMA2(s0, w[2], A[i][2], s0);
        FMA2(s1, w[6], A[i][6], s1);
        FMA2(s0, w[3], A[i][3], s0);
        FMA2(s1, w[7], A[i][7], s1);
        ADD2(s0, s0, s1);
        float lo, hi;
        UNPACK2(lo, hi, s0);
        o[i] = lo + hi;
    }

    float4* o4 = (float4*)(out + pos * 16 + half * 8);
    o4[0] = make_float4(o[0], o[1], o[2], o[3]);
    o4[1] = make_float4(o[4], o[5], o[6], o[7]);
}

extern "C" void kernel_launch(void* const* d_in, const int* in_sizes, int n_in,
                              void* d_out, int out_size) {
    const float* data  = (const float*)d_in[0];
    const float* paras = (const float*)d_in[1];
    if (n_in >= 2 && in_sizes[0] > in_sizes[1]) {  // defensive ordering by size
        data  = (const float*)d_in[1];
        paras = (const float*)d_in[0];
    }
    inv1x1mm_svd_kernel<<<NPOS / 32, 64>>>(data, paras, (float*)d_out);
}

// round 17
// speedup vs baseline: 2.8219x; 1.0788x over previous
#include <cuda_runtime.h>
#include <cstdint>

// Inv1x1MM_SVD, C=16, 65536 positions.
// R10 base (2-lane row-slab MGS, fresh norms, rs0->smem, rs1 folded into w)
// with: (1) fused per-column dot->update in the MGS step (pp[8] array gone:
// less register-scheduling pressure at the step-0 peak), (2) ls loaded as
// 4x LDG.128 under the V-load shadow and folded into the PARTIAL w before
// the pair-reduce (linear, exact), halving ls load ops and hiding latency.

constexpr int NPOS = 8 * 8192;

#define FMA2(d, a, b, c) asm("fma.rn.f32x2 %0, %1, %2, %3;" : "=l"(d) : "l"(a), "l"(b), "l"(c))
#define MUL2(d, a, b)    asm("mul.rn.f32x2 %0, %1, %2;"     : "=l"(d) : "l"(a), "l"(b))
#define ADD2(d, a, b)    asm("add.rn.f32x2 %0, %1, %2;"     : "=l"(d) : "l"(a), "l"(b))
#define PACK2(d, lo, hi) asm("mov.b64 %0, {%1, %2};"        : "=l"(d) : "f"(lo), "f"(hi))
#define UNPACK2(lo, hi, d) asm("mov.b64 {%0, %1}, %2;" : "=f"(lo), "=f"(hi) : "l"(d))

__device__ __forceinline__ uint64_t shx1(uint64_t v) {
    uint32_t lo, hi;
    asm("mov.b64 {%0, %1}, %2;" : "=r"(lo), "=r"(hi) : "l"(v));
    lo = __shfl_xor_sync(0xffffffffu, lo, 1);
    hi = __shfl_xor_sync(0xffffffffu, hi, 1);
    uint64_t r;
    asm("mov.b64 %0, {%1, %2};" : "=l"(r) : "r"(lo), "r"(hi));
    return r;
}
__device__ __forceinline__ float frcp(float x) {
    float r;
    asm("rcp.approx.f32 %0, %1;" : "=f"(r) : "f"(x));
    return r;
}

// pair-dot of ak (duplicated column k) against column pair c, reduced over
// the lane pair: returns packed <c_k, c_{2c}>, <c_k, c_{2c+1}>
__device__ __forceinline__ uint64_t pairdot(const uint64_t (&ak)[8],
                                            const uint64_t (&A)[8][8], int c) {
    uint64_t s0, s1;
    MUL2(s0, ak[0], A[0][c]);
    MUL2(s1, ak[4], A[4][c]);
    FMA2(s0, ak[1], A[1][c], s0);
    FMA2(s1, ak[5], A[5][c], s1);
    FMA2(s0, ak[2], A[2][c], s0);
    FMA2(s1, ak[6], A[6][c], s1);
    FMA2(s0, ak[3], A[3][c], s0);
    FMA2(s1, ak[7], A[7][c], s1);
    ADD2(s0, s0, s1);
    const uint64_t o = shx1(s0);
    ADD2(s0, s0, o);
    return s0;
}

// MGS, rows split across a lane pair. Fused per-column dot->update.
// SCALEW=false: writer lane stores 1/||b_k|| to rs_sm[k].
// SCALEW=true : fold 1/||b_k|| into w element k as columns finish.
template <bool SCALEW>
__device__ __forceinline__ void mgs2(uint64_t (&A)[8][8], uint64_t* w,
                                     float* rs_sm, bool writer) {
    #pragma unroll
    for (int k = 0; k < 15; k++) {
        const int c0 = k >> 1;
        const int cu = (k + 1) >> 1;

        uint64_t ak[8];
        #pragma unroll
        for (int i = 0; i < 8; i++) {
            float lo, hi;
            UNPACK2(lo, hi, A[i][c0]);
            const float x = (k & 1) ? hi : lo;
            PACK2(ak[i], x, x);
        }

        // dot for pair c0 first: gives the FRESH norm ||c_k||^2
        const uint64_t p0 = pairdot(ak, A, c0);
        float plo, phi;
        UNPACK2(plo, phi, p0);
        const float pk = fmaxf((k & 1) ? phi : plo, 1e-30f);
        const float ninv = -frcp(pk);        // projection path (MUFU.RCP)
        const float r = rsqrtf(pk);          // normalization path (parallel)
        if (SCALEW) {
            float wl, wh;
            UNPACK2(wl, wh, w[c0]);
            if (k & 1) wh *= r; else wl *= r;
            PACK2(w[c0], wl, wh);
        } else if (writer) {
            rs_sm[k] = r;
        }
        uint64_t n2;
        PACK2(n2, ninv, ninv);

        // fused: per column pair, dot (or reuse p0) -> scale -> update
        #pragma unroll
        for (int c = cu; c < 8; c++) {
            uint64_t pc;
            if (c == c0) pc = p0;           // k even: within-pair coupling
            else         pc = pairdot(ak, A, c);
            uint64_t s;
            MUL2(s, pc, n2);
            if (!(k & 1) && c == cu) {       // pair contains j == k: mask lo half
                float sl, sh;
                UNPACK2(sl, sh, s);
                PACK2(s, 0.0f, sh);
            }
            #pragma unroll
            for (int i = 0; i < 8; i++) FMA2(A[i][c], s, ak[i], A[i][c]);
        }
    }
    // column 15 norm
    float n15 = 0.0f;
    #pragma unroll
    for (int i = 0; i < 8; i++) {
        float lo, hi;
        UNPACK2(lo, hi, A[i][7]);
        n15 = fmaf(hi, hi, n15);
    }
    n15 += __shfl_xor_sync(0xffffffffu, n15, 1);
    const float r = rsqrtf(fmaxf(n15, 1e-30f));
    if (SCALEW) {
        float wl, wh;
        UNPACK2(wl, wh, w[7]);
        wh *= r;
        PACK2(w[7], wl, wh);
    } else if (writer) {
        rs_sm[15] = r;
    }
}

__device__ __forceinline__ void load_mat(uint64_t (&A)[8][8], const float4* f4, int rbase) {
    #pragma unroll
    for (int i = 0; i < 8; i++) {
        const float4 q0 = __ldg(&f4[rbase + 4 * i + 0]);
        const float4 q1 = __ldg(&f4[rbase + 4 * i + 1]);
        const float4 q2 = __ldg(&f4[rbase + 4 * i + 2]);
        const float4 q3 = __ldg(&f4[rbase + 4 * i + 3]);
        PACK2(A[i][0], q0.x, q0.y); PACK2(A[i][1], q0.z, q0.w);
        PACK2(A[i][2], q1.x, q1.y); PACK2(A[i][3], q1.z, q1.w);
        PACK2(A[i][4], q2.x, q2.y); PACK2(A[i][5], q2.z, q2.w);
        PACK2(A[i][6], q3.x, q3.y); PACK2(A[i][7], q3.z, q3.w);
    }
}

__global__ void __launch_bounds__(64, 6)
inv1x1mm_svd_kernel(const float* __restrict__ data,
                    const float* __restrict__ paras,
                    float* __restrict__ out) {
    __shared__ float rs_sm[32][17];          // U inverse norms, stride-17

    const int tid  = threadIdx.x;
    const int half = tid & 1;
    const int p    = tid >> 1;
    const int pos  = blockIdx.x * 32 + p;

    const float4* f4 = (const float4*)paras + (size_t)pos * 132;

    uint64_t A[8][8];

    // ===== QR of U =====  (rs0 -> rs_sm)
    load_mat(A, f4, 4 + half * 32);
    mgs2<false>(A, nullptr, rs_sm[p], half == 0);

    // local partial dots v_j against U's Q (before A is reloaded with V)
    const float4 d0 = __ldg((const float4*)(data + pos * 16 + half * 8));
    const float4 d1 = __ldg((const float4*)(data + pos * 16 + half * 8 + 4));
    uint64_t dd[8];
    PACK2(dd[0], d0.x, d0.x); PACK2(dd[1], d0.y, d0.y);
    PACK2(dd[2], d0.z, d0.z); PACK2(dd[3], d0.w, d0.w);
    PACK2(dd[4], d1.x, d1.x); PACK2(dd[5], d1.y, d1.y);
    PACK2(dd[6], d1.z, d1.z); PACK2(dd[7], d1.w, d1.w);

    uint64_t w[8];
    #pragma unroll
    for (int c = 0; c < 8; c++) {
        uint64_t s0, s1;
        MUL2(s0, dd[0], A[0][c]);
        MUL2(s1, dd[4], A[4][c]);
        FMA2(s0, dd[1], A[1][c], s0);
        FMA2(s1, dd[5], A[5][c], s1);
        FMA2(s0, dd[2], A[2][c], s0);
        FMA2(s1, dd[6], A[6][c], s1);
        FMA2(s0, dd[3], A[3][c], s0);
        FMA2(s1, dd[7], A[7][c], s1);
        ADD2(w[c], s0, s1);                  // PARTIAL (not yet pair-reduced)
    }

    // issue V loads first (long pole), then ls loads under their shadow
    load_mat(A, f4, 68 + half * 32);
    const float4 l0 = __ldg(&f4[0]);
    const float4 l1 = __ldg(&f4[1]);
    const float4 l2 = __ldg(&f4[2]);
    const float4 l3 = __ldg(&f4[3]);

    __syncwarp();   // partner's rs_sm writes -> my reads
    // scale PARTIAL w by exp(ls)*rs0 (linear: exact before the pair-reduce),
    // then reduce across the lane pair.
    {
        uint64_t m;
        PACK2(m, __expf(l0.x) * rs_sm[p][0],  __expf(l0.y) * rs_sm[p][1]);
        MUL2(w[0], w[0], m);
        PACK2(m, __expf(l0.z) * rs_sm[p][2],  __expf(l0.w) * rs_sm[p][3]);
        MUL2(w[1], w[1], m);
        PACK2(m, __expf(l1.x) * rs_sm[p][4],  __expf(l1.y) * rs_sm[p][5]);
        MUL2(w[2], w[2], m);
        PACK2(m, __expf(l1.z) * rs_sm[p][6],  __expf(l1.w) * rs_sm[p][7]);
        MUL2(w[3], w[3], m);
        PACK2(m, __expf(l2.x) * rs_sm[p][8],  __expf(l2.y) * rs_sm[p][9]);
        MUL2(w[4], w[4], m);
        PACK2(m, __expf(l2.z) * rs_sm[p][10], __expf(l2.w) * rs_sm[p][11]);
        MUL2(w[5], w[5], m);
        PACK2(m, __expf(l3.x) * rs_sm[p][12], __expf(l3.y) * rs_sm[p][13]);
        MUL2(w[6], w[6], m);
        PACK2(m, __expf(l3.z) * rs_sm[p][14], __expf(l3.w) * rs_sm[p][15]);
        MUL2(w[7], w[7], m);
    }
    #pragma unroll
    for (int c = 0; c < 8; c++) {
        const uint64_t o = shx1(w[c]);
        ADD2(w[c], w[c], o);
    }

    // ===== QR of V =====  (folds 1/||b1_j|| into w)
    mgs2<true>(A, w, nullptr, false);

    // res_d = sum_j w_j * b1[d][j]  (d = my 8 local rows)
    float o[8];
    #pragma unroll
    for (int i = 0; i < 8; i++) {
        uint64_t s0, s1;
        MUL2(s0, w[0], A[i][0]);
        MUL2(s1, w[4], A[i][4]);
        FMA2(s0, w[1], A[i][1], s0);
        FMA2(s1, w[5], A[i][5], s1);
        FMA2(s0, w[2], A[i][2], s0);
        FMA2(s1, w[6], A[i][6], s1);
        FMA2(s0, w[3], A[i][3], s0);
        FMA2(s1, w[7], A[i][7], s1);
        ADD2(s0, s0, s1);
        float lo, hi;
        UNPACK2(lo, hi, s0);
        o[i] = lo + hi;
    }

    float4* o4 = (float4*)(out + pos * 16 + half * 8);
    o4[0] = make_float4(o[0], o[1], o[2], o[3]);
    o4[1] = make_float4(o[4], o[5], o[6], o[7]);
}

extern "C" void kernel_launch(void* const* d_in, const int* in_sizes, int n_in,
                              void* d_out, int out_size) {
    const float* data  = (const float*)d_in[0];
    const float* paras = (const float*)d_in[1];
    if (n_in >= 2 && in_sizes[0] > in_sizes[1]) {  // defensive ordering by size
        data  = (const float*)d_in[1];
        paras = (const float*)d_in[0];
    }
    inv1x1mm_svd_kernel<<<NPOS / 32, 64>>>(data, paras, (float*)d_out);
}